// round 4
// baseline (speedup 1.0000x reference)
#include <cuda_runtime.h>
#include <cuda_bf16.h>

#define BN  32            // images
#define BPI 32            // blocks per image
#define NBLK (BN * BPI)   // 1024

// Per-block partials: [NBLK][3 scales][5] = {C, S, inter, z, psum}
__device__ float g_part[NBLK * 15];
__device__ unsigned g_count = 0;

__device__ __forceinline__ float warp_sum(float v) {
    #pragma unroll
    for (int o = 16; o > 0; o >>= 1) v += __shfl_down_sync(0xffffffffu, v, o);
    return v;
}

__device__ __forceinline__ float fsigmoid(float x) {
    return __fdividef(1.0f, 1.0f + __expf(-x));
}

struct Acc { float c, s, inter, z, ps; };

// Block reduce + write this block's partial slot for scale sc.
__device__ __forceinline__ void commit(Acc a, int sc, float* s_red) {
    a.c     = warp_sum(a.c);
    a.s     = warp_sum(a.s);
    a.inter = warp_sum(a.inter);
    a.z     = warp_sum(a.z);
    a.ps    = warp_sum(a.ps);
    const int wid = threadIdx.x >> 5;
    if ((threadIdx.x & 31) == 0) {
        float* r = s_red + wid * 5;
        r[0] = a.c; r[1] = a.s; r[2] = a.inter; r[3] = a.z; r[4] = a.ps;
    }
    __syncthreads();
    if (threadIdx.x == 0) {
        float o0 = 0.f, o1 = 0.f, o2 = 0.f, o3 = 0.f, o4 = 0.f;
        #pragma unroll
        for (int w = 0; w < 8; w++) {
            o0 += s_red[w * 5 + 0]; o1 += s_red[w * 5 + 1]; o2 += s_red[w * 5 + 2];
            o3 += s_red[w * 5 + 3]; o4 += s_red[w * 5 + 4];
        }
        float* g = &g_part[(blockIdx.x * 3 + sc) * 5];
        g[0] = o0; g[1] = o1; g[2] = o2; g[3] = o3; g[4] = o4;
    }
    __syncthreads();
}

// ---- scale 0: 512x512, stride 1, vec4 ----
__device__ Acc do_scale0(const float* __restrict__ lg, const int* __restrict__ tg, int tpi_tid) {
    Acc a = {0.f, 0.f, 0.f, 0.f, 0.f};
    const int nvec = 512 * 512 / 4;
    const int stride = BPI * 256;
    #pragma unroll 2
    for (int v = tpi_tid; v < nvec; v += stride) {
        const int p  = v << 2;
        const int ii = p >> 9;
        const int jj = p & 511;

        const float4 xl = *reinterpret_cast<const float4*>(lg + p);
        const int4   tc = *reinterpret_cast<const int4*>(tg + p);

        float px[4] = { fsigmoid(xl.x), fsigmoid(xl.y), fsigmoid(xl.z), fsigmoid(xl.w) };
        int  tcs[4] = { tc.x, tc.y, tc.z, tc.w };
        a.ps += px[0] + px[1] + px[2] + px[3];
        a.z  += px[0]*px[0] + px[1]*px[1] + px[2]*px[2] + px[3]*px[3];

        if (tc.x | tc.y | tc.z | tc.w) {
            int4 tu = make_int4(0,0,0,0), td = make_int4(0,0,0,0);
            if (ii > 0)   tu = *reinterpret_cast<const int4*>(tg + p - 512);
            if (ii < 511) td = *reinterpret_cast<const int4*>(tg + p + 512);
            const int tl = (jj > 0)   ? tg[p - 1] : 0;
            const int tr = (jj < 508) ? tg[p + 4] : 0;

            int tus[4] = { tu.x, tu.y, tu.z, tu.w };
            int tds[4] = { td.x, td.y, td.z, td.w };
            int lf[4]  = { tl, tc.x, tc.y, tc.z };
            int rt[4]  = { tc.y, tc.z, tc.w, tr };
            #pragma unroll
            for (int l = 0; l < 4; l++) {
                if (tcs[l]) {
                    a.s     += 1.0f;
                    a.inter += px[l];
                    if (1 + tus[l] + tds[l] + lf[l] + rt[l] != 5) a.c += 1.0f;
                }
            }
        }
    }
    return a;
}

// ---- scale 1: 256x256, target stride 2, vec4 with int4 target loads ----
__device__ Acc do_scale1(const float* __restrict__ lg, const int* __restrict__ tg, int tpi_tid) {
    Acc a = {0.f, 0.f, 0.f, 0.f, 0.f};
    const int nvec = 256 * 256 / 4;
    const int stride = BPI * 256;
    #pragma unroll 2
    for (int v = tpi_tid; v < nvec; v += stride) {
        const int p  = v << 2;
        const int ii = p >> 8;          // row in 256
        const int jj = p & 255;         // col start (multiple of 4)
        const int b  = (ii << 10) + (jj << 1);   // ii*2*512 + jj*2 (int4 aligned)

        const float4 xl = *reinterpret_cast<const float4*>(lg + p);
        const int4 A = *reinterpret_cast<const int4*>(tg + b);
        const int4 Bv = *reinterpret_cast<const int4*>(tg + b + 4);
        int tcs[4] = { A.x, A.z, Bv.x, Bv.z };

        float px[4] = { fsigmoid(xl.x), fsigmoid(xl.y), fsigmoid(xl.z), fsigmoid(xl.w) };
        a.ps += px[0] + px[1] + px[2] + px[3];
        a.z  += px[0]*px[0] + px[1]*px[1] + px[2]*px[2] + px[3]*px[3];

        if (tcs[0] | tcs[1] | tcs[2] | tcs[3]) {
            int tus[4] = {0,0,0,0}, tds[4] = {0,0,0,0};
            if (ii > 0) {
                const int4 u0 = *reinterpret_cast<const int4*>(tg + b - 1024);
                const int4 u1 = *reinterpret_cast<const int4*>(tg + b - 1024 + 4);
                tus[0] = u0.x; tus[1] = u0.z; tus[2] = u1.x; tus[3] = u1.z;
            }
            if (ii < 255) {
                const int4 d0 = *reinterpret_cast<const int4*>(tg + b + 1024);
                const int4 d1 = *reinterpret_cast<const int4*>(tg + b + 1024 + 4);
                tds[0] = d0.x; tds[1] = d0.z; tds[2] = d1.x; tds[3] = d1.z;
            }
            const int tl = (jj > 0)   ? tg[b - 2] : 0;
            const int tr = (jj < 252) ? tg[b + 8] : 0;
            int lf[4] = { tl, tcs[0], tcs[1], tcs[2] };
            int rt[4] = { tcs[1], tcs[2], tcs[3], tr };
            #pragma unroll
            for (int l = 0; l < 4; l++) {
                if (tcs[l]) {
                    a.s     += 1.0f;
                    a.inter += px[l];
                    if (1 + tus[l] + tds[l] + lf[l] + rt[l] != 5) a.c += 1.0f;
                }
            }
        }
    }
    return a;
}

// ---- scale 2: 128x128, target stride 4, scalar ----
__device__ Acc do_scale2(const float* __restrict__ lg, const int* __restrict__ tg, int tpi_tid) {
    Acc a = {0.f, 0.f, 0.f, 0.f, 0.f};
    const int npix = 128 * 128;
    const int stride = BPI * 256;
    #pragma unroll 2
    for (int p = tpi_tid; p < npix; p += stride) {
        const int ii = p >> 7;
        const int jj = p & 127;
        const int b  = (ii << 11) + (jj << 2);   // ii*4*512 + jj*4

        const int   t  = tg[b];
        const float pr = fsigmoid(lg[p]);
        a.ps += pr;
        a.z  += pr * pr;
        if (t) {
            a.s     += 1.0f;
            a.inter += pr;
            int sum = 1;
            sum += (ii > 0)   ? tg[b - 2048] : 0;
            sum += (ii < 127) ? tg[b + 2048] : 0;
            sum += (jj > 0)   ? tg[b - 4]    : 0;
            sum += (jj < 127) ? tg[b + 4]    : 0;
            if (sum != 5) a.c += 1.0f;
        }
    }
    return a;
}

__global__ void __launch_bounds__(256)
fused_kernel(const float* __restrict__ l0,
             const float* __restrict__ l1,
             const float* __restrict__ l2,
             const int*   __restrict__ tg,
             const float* __restrict__ vm,
             float* __restrict__ out) {
    __shared__ float s_red[8 * 5];
    __shared__ bool  s_last;
    __shared__ float s_contrib[96];
    __shared__ float s_valid[BN];

    const int img = blockIdx.x >> 5;
    const int blk = blockIdx.x & 31;
    const int tpi_tid = blk * 256 + threadIdx.x;   // thread index within image's 8192 threads

    const float* lg0 = l0 + (size_t)img * 512 * 512;
    const float* lg1 = l1 + (size_t)img * 256 * 256;
    const float* lg2 = l2 + (size_t)img * 128 * 128;
    const int*   tgi = tg + (size_t)img * 512 * 512;

    commit(do_scale0(lg0, tgi, tpi_tid), 0, s_red);
    commit(do_scale1(lg1, tgi, tpi_tid), 1, s_red);
    commit(do_scale2(lg2, tgi, tpi_tid), 2, s_red);

    if (threadIdx.x == 0) {
        __threadfence();
        unsigned r = atomicAdd(&g_count, 1u);
        s_last = (r == NBLK - 1);
    }
    __syncthreads();
    if (!s_last) return;

    const int tid = threadIdx.x;
    if (tid == 0) g_count = 0;
    if (tid < BN) s_valid[tid] = (vm[tid] >= 0.5f) ? 1.0f : 0.0f;
    __syncthreads();

    if (tid < 96) {
        const int sc  = tid >> 5;
        const int im  = tid & 31;
        float C = 0.f, S = 0.f, I = 0.f, Z = 0.f, P = 0.f;
        for (int b = 0; b < BPI; b++) {
            const float* g = &g_part[(((im << 5) + b) * 3 + sc) * 5];
            C += g[0]; S += g[1]; I += g[2]; Z += g[3]; P += g[4];
        }
        const float SMOOTH = 1e-5f;
        const float ws[3]     = { 1.0f / 1.75f, 0.5f / 1.75f, 0.25f / 1.75f };
        const float inv_hw[3] = { 1.0f / (512.f * 512.f), 1.0f / (256.f * 256.f), 1.0f / (128.f * 128.f) };
        float alpha = 2.0f * (1.0f - (C + SMOOTH) / (S + SMOOTH)) - 1.0f;
        alpha = fminf(alpha, 0.8f);
        const float num = Z + S - 2.0f * I + SMOOTH;
        const float den = Z + S - (1.0f + alpha) * I + SMOOTH;
        const float dou = num / den;
        const float per = (S > 0.f) ? dou : P * inv_hw[sc];
        s_contrib[tid] = ws[sc] * per * s_valid[im];
    }
    __syncthreads();
    if (tid == 0) {
        float sum = 0.f, cnt = 0.f;
        #pragma unroll
        for (int i = 0; i < 96; i++) sum += s_contrib[i];
        #pragma unroll
        for (int i = 0; i < BN; i++) cnt += s_valid[i];
        out[0] = (cnt > 0.f) ? (sum / cnt) : 0.0f;
    }
}

extern "C" void kernel_launch(void* const* d_in, const int* in_sizes, int n_in,
                              void* d_out, int out_size) {
    const float* l0 = (const float*)d_in[0];
    const float* l1 = (const float*)d_in[1];
    const float* l2 = (const float*)d_in[2];
    const int*   tg = (const int*)d_in[3];
    const float* vm = (const float*)d_in[4];
    float* out = (float*)d_out;

    fused_kernel<<<NBLK, 256>>>(l0, l1, l2, tg, vm, out);
}

// round 5
// speedup vs baseline: 1.1742x; 1.1742x over previous
#include <cuda_runtime.h>
#include <cuda_bf16.h>

#define BN 32
#define BPI2 8
#define BPI1 16
#define BPI0 32
#define NB2 (BN * BPI2)            // 256
#define NB1 (BN * BPI1)            // 512
#define NB0 (BN * BPI0)            // 1024
#define NBLK (NB2 + NB1 + NB0)     // 1792

// Per-block partials: [NBLK][5] = {C, S, inter, z, psum}
__device__ float g_part[NBLK * 5];
__device__ unsigned g_count = 0;

__device__ __forceinline__ float warp_sum(float v) {
    #pragma unroll
    for (int o = 16; o > 0; o >>= 1) v += __shfl_down_sync(0xffffffffu, v, o);
    return v;
}

__device__ __forceinline__ float fsigmoid(float x) {
    return __fdividef(1.0f, 1.0f + __expf(-x));
}

struct Acc { float c, s, inter, z, ps; };

__device__ __forceinline__ void commit(Acc& a, int slot, float* s_red) {
    a.c     = warp_sum(a.c);
    a.s     = warp_sum(a.s);
    a.inter = warp_sum(a.inter);
    a.z     = warp_sum(a.z);
    a.ps    = warp_sum(a.ps);
    const int wid = threadIdx.x >> 5;
    if ((threadIdx.x & 31) == 0) {
        float* r = s_red + wid * 5;
        r[0] = a.c; r[1] = a.s; r[2] = a.inter; r[3] = a.z; r[4] = a.ps;
    }
    __syncthreads();
    if (threadIdx.x == 0) {
        float o0 = 0.f, o1 = 0.f, o2 = 0.f, o3 = 0.f, o4 = 0.f;
        #pragma unroll
        for (int w = 0; w < 8; w++) {
            o0 += s_red[w * 5 + 0]; o1 += s_red[w * 5 + 1]; o2 += s_red[w * 5 + 2];
            o3 += s_red[w * 5 + 3]; o4 += s_red[w * 5 + 4];
        }
        float* g = &g_part[slot * 5];
        g[0] = o0; g[1] = o1; g[2] = o2; g[3] = o3; g[4] = o4;
    }
}

// Per-vector body for scale-0 (unconditional neighbor loads for MLP).
__device__ __forceinline__ void s0_body(const float* __restrict__ lg,
                                        const int*   __restrict__ tg,
                                        int v, Acc& a) {
    const int p  = v << 2;
    const int ii = p >> 9;
    const int jj = p & 511;

    const float4 xl = *reinterpret_cast<const float4*>(lg + p);
    const int4   tc = *reinterpret_cast<const int4*>(tg + p);
    // Unconditional, clamped neighbor addresses; value masked after load.
    const int4 tuL = *reinterpret_cast<const int4*>(tg + (ii > 0   ? p - 512 : p));
    const int4 tdL = *reinterpret_cast<const int4*>(tg + (ii < 511 ? p + 512 : p));
    const int  tlL = tg[jj > 0   ? p - 1 : p];
    const int  trL = tg[jj < 508 ? p + 4 : p];

    const int mu = (ii > 0)   ? ~0 : 0;
    const int md = (ii < 511) ? ~0 : 0;
    const int tl = (jj > 0)   ? tlL : 0;
    const int tr = (jj < 508) ? trL : 0;

    float px[4] = { fsigmoid(xl.x), fsigmoid(xl.y), fsigmoid(xl.z), fsigmoid(xl.w) };
    a.ps += px[0] + px[1] + px[2] + px[3];
    a.z  += px[0]*px[0] + px[1]*px[1] + px[2]*px[2] + px[3]*px[3];

    int tcs[4] = { tc.x, tc.y, tc.z, tc.w };
    int tus[4] = { tuL.x & mu, tuL.y & mu, tuL.z & mu, tuL.w & mu };
    int tds[4] = { tdL.x & md, tdL.y & md, tdL.z & md, tdL.w & md };
    int lf[4]  = { tl, tc.x, tc.y, tc.z };
    int rt[4]  = { tc.y, tc.z, tc.w, tr };
    #pragma unroll
    for (int l = 0; l < 4; l++) {
        if (tcs[l]) {
            a.s     += 1.0f;
            a.inter += px[l];
            if (1 + tus[l] + tds[l] + lf[l] + rt[l] != 5) a.c += 1.0f;
        }
    }
}

// ---- scale 0: 512x512, vec4, 8 iterations unrolled 2 ----
__device__ Acc do_scale0(const float* __restrict__ logits,
                         const int*   __restrict__ targets,
                         int img, int blk) {
    const float* __restrict__ lg = logits  + (size_t)img * 512 * 512;
    const int*   __restrict__ tg = targets + (size_t)img * 512 * 512;

    Acc a = {0.f, 0.f, 0.f, 0.f, 0.f};
    const int stride = BPI0 * 256;            // 8192 threads per image
    int v = blk * 256 + threadIdx.x;          // 8 iterations over 65536 vectors
    #pragma unroll
    for (int it = 0; it < 4; it++) {
        s0_body(lg, tg, v, a);
        s0_body(lg, tg, v + stride, a);
        v += 2 * stride;
    }
    return a;
}

// ---- scale 1: 256x256, target stride 2, vec4 + int4 target loads ----
__device__ Acc do_scale1(const float* __restrict__ logits,
                         const int*   __restrict__ targets,
                         int img, int blk) {
    const float* __restrict__ lg = logits  + (size_t)img * 256 * 256;
    const int*   __restrict__ tg = targets + (size_t)img * 512 * 512;

    Acc a = {0.f, 0.f, 0.f, 0.f, 0.f};
    const int stride = BPI1 * 256;            // 4096 threads per image
    int v = blk * 256 + threadIdx.x;          // 4 iterations over 16384 vectors
    #pragma unroll
    for (int it = 0; it < 4; it++, v += stride) {
        const int p  = v << 2;
        const int ii = p >> 8;
        const int jj = p & 255;
        const int b  = (ii << 10) + (jj << 1);

        const float4 xl = *reinterpret_cast<const float4*>(lg + p);
        const int4 A  = *reinterpret_cast<const int4*>(tg + b);
        const int4 Bv = *reinterpret_cast<const int4*>(tg + b + 4);
        const int4 u0 = *reinterpret_cast<const int4*>(tg + (ii > 0   ? b - 1024 : b));
        const int4 u1 = *reinterpret_cast<const int4*>(tg + (ii > 0   ? b - 1020 : b));
        const int4 d0 = *reinterpret_cast<const int4*>(tg + (ii < 255 ? b + 1024 : b));
        const int4 d1 = *reinterpret_cast<const int4*>(tg + (ii < 255 ? b + 1028 : b));
        const int  tlL = tg[jj > 0   ? b - 2 : b];
        const int  trL = tg[jj < 252 ? b + 8 : b];

        const int mu = (ii > 0)   ? ~0 : 0;
        const int md = (ii < 255) ? ~0 : 0;
        const int tl = (jj > 0)   ? tlL : 0;
        const int tr = (jj < 252) ? trL : 0;

        float px[4] = { fsigmoid(xl.x), fsigmoid(xl.y), fsigmoid(xl.z), fsigmoid(xl.w) };
        a.ps += px[0] + px[1] + px[2] + px[3];
        a.z  += px[0]*px[0] + px[1]*px[1] + px[2]*px[2] + px[3]*px[3];

        int tcs[4] = { A.x, A.z, Bv.x, Bv.z };
        int tus[4] = { u0.x & mu, u0.z & mu, u1.x & mu, u1.z & mu };
        int tds[4] = { d0.x & md, d0.z & md, d1.x & md, d1.z & md };
        int lf[4]  = { tl, tcs[0], tcs[1], tcs[2] };
        int rt[4]  = { tcs[1], tcs[2], tcs[3], tr };
        #pragma unroll
        for (int l = 0; l < 4; l++) {
            if (tcs[l]) {
                a.s     += 1.0f;
                a.inter += px[l];
                if (1 + tus[l] + tds[l] + lf[l] + rt[l] != 5) a.c += 1.0f;
            }
        }
    }
    return a;
}

// ---- scale 2: 128x128, target stride 4, scalar, unconditional loads ----
__device__ Acc do_scale2(const float* __restrict__ logits,
                         const int*   __restrict__ targets,
                         int img, int blk) {
    const float* __restrict__ lg = logits  + (size_t)img * 128 * 128;
    const int*   __restrict__ tg = targets + (size_t)img * 512 * 512;

    Acc a = {0.f, 0.f, 0.f, 0.f, 0.f};
    const int stride = BPI2 * 256;            // 2048 threads per image
    int p = blk * 256 + threadIdx.x;          // 8 iterations over 16384 pixels
    #pragma unroll
    for (int it = 0; it < 8; it++, p += stride) {
        const int ii = p >> 7;
        const int jj = p & 127;
        const int b  = (ii << 11) + (jj << 2);

        const float x = lg[p];
        const int t   = tg[b];
        const int tuL = tg[ii > 0   ? b - 2048 : b];
        const int tdL = tg[ii < 127 ? b + 2048 : b];
        const int tlL = tg[jj > 0   ? b - 4    : b];
        const int trL = tg[jj < 127 ? b + 4    : b];

        const float pr = fsigmoid(x);
        a.ps += pr;
        a.z  += pr * pr;
        if (t) {
            a.s     += 1.0f;
            a.inter += pr;
            int sum = 1;
            sum += (ii > 0)   ? tuL : 0;
            sum += (ii < 127) ? tdL : 0;
            sum += (jj > 0)   ? tlL : 0;
            sum += (jj < 127) ? trL : 0;
            if (sum != 5) a.c += 1.0f;
        }
    }
    return a;
}

__global__ void __launch_bounds__(256)
fused_kernel(const float* __restrict__ l0,
             const float* __restrict__ l1,
             const float* __restrict__ l2,
             const int*   __restrict__ tg,
             const float* __restrict__ vm,
             float* __restrict__ out) {
    __shared__ float s_red[8 * 5];
    __shared__ bool  s_last;
    __shared__ float s_contrib[96];
    __shared__ float s_valid[BN];

    const int bid = blockIdx.x;
    Acc a;
    if (bid < NB2) {
        a = do_scale2(l2, tg, bid / BPI2, bid % BPI2);
    } else if (bid < NB2 + NB1) {
        const int b = bid - NB2;
        a = do_scale1(l1, tg, b / BPI1, b % BPI1);
    } else {
        const int b = bid - NB2 - NB1;
        a = do_scale0(l0, tg, b / BPI0, b % BPI0);
    }
    commit(a, bid, s_red);

    __syncthreads();
    if (threadIdx.x == 0) {
        __threadfence();
        unsigned r = atomicAdd(&g_count, 1u);
        s_last = (r == NBLK - 1);
    }
    __syncthreads();
    if (!s_last) return;

    const int tid = threadIdx.x;
    if (tid == 0) g_count = 0;
    if (tid < BN) s_valid[tid] = (vm[tid] >= 0.5f) ? 1.0f : 0.0f;
    __syncthreads();

    if (tid < 96) {
        const int sc  = tid >> 5;   // 0=scale0, 1=scale1, 2=scale2
        const int img = tid & 31;
        int base, cntb;
        if      (sc == 0) { base = (NB2 + NB1) + img * BPI0; cntb = BPI0; }
        else if (sc == 1) { base = NB2 + img * BPI1;         cntb = BPI1; }
        else              { base = img * BPI2;               cntb = BPI2; }

        float C = 0.f, S = 0.f, I = 0.f, Z = 0.f, P = 0.f;
        for (int b = 0; b < cntb; b++) {
            const float* g = &g_part[(base + b) * 5];
            C += g[0]; S += g[1]; I += g[2]; Z += g[3]; P += g[4];
        }
        const float SMOOTH = 1e-5f;
        const float ws[3]     = { 1.0f / 1.75f, 0.5f / 1.75f, 0.25f / 1.75f };
        const float inv_hw[3] = { 1.0f / (512.f * 512.f), 1.0f / (256.f * 256.f), 1.0f / (128.f * 128.f) };
        float alpha = 2.0f * (1.0f - (C + SMOOTH) / (S + SMOOTH)) - 1.0f;
        alpha = fminf(alpha, 0.8f);
        const float num = Z + S - 2.0f * I + SMOOTH;
        const float den = Z + S - (1.0f + alpha) * I + SMOOTH;
        const float dou = num / den;
        const float per = (S > 0.f) ? dou : P * inv_hw[sc];
        s_contrib[tid] = ws[sc] * per * s_valid[img];
    }
    __syncthreads();
    if (tid == 0) {
        float sum = 0.f, cnt = 0.f;
        #pragma unroll
        for (int i = 0; i < 96; i++) sum += s_contrib[i];
        #pragma unroll
        for (int i = 0; i < BN; i++) cnt += s_valid[i];
        out[0] = (cnt > 0.f) ? (sum / cnt) : 0.0f;
    }
}

extern "C" void kernel_launch(void* const* d_in, const int* in_sizes, int n_in,
                              void* d_out, int out_size) {
    const float* l0 = (const float*)d_in[0];
    const float* l1 = (const float*)d_in[1];
    const float* l2 = (const float*)d_in[2];
    const int*   tg = (const int*)d_in[3];
    const float* vm = (const float*)d_in[4];
    float* out = (float*)d_out;

    fused_kernel<<<NBLK, 256>>>(l0, l1, l2, tg, vm, out);
}